// round 1
// baseline (speedup 1.0000x reference)
#include <cuda_runtime.h>
#include <cuda_bf16.h>
#include <math_constants.h>

#define TOKENS  32768
#define DIM     2048
#define NE      64
#define TOPK    6
#define TPC     128     // tokens (== threads) per CTA
#define KC      16      // K-chunk staged in shared memory

// Fully fused gate kernel:
//   per-thread: 64 fp32 accumulators (one token x all experts),
//   smem-broadcast weight chunks, register softmax + bias + top-6.
__global__ __launch_bounds__(TPC, 2)
void gate_fused_kernel(const float* __restrict__ x,
                       const float* __restrict__ w,
                       const float* __restrict__ bias,
                       float* __restrict__ out) {
    __shared__ float xs[TPC][KC + 4];   // +4 pad keeps 16B alignment, breaks bank stride
    __shared__ float ws[KC][NE];        // transposed weight chunk: ws[kk][e]
    __shared__ float bs[NE];

    const int tid = threadIdx.x;
    const int t0  = blockIdx.x * TPC;

    if (tid < NE) bs[tid] = bias[tid];

    float acc[NE];
#pragma unroll
    for (int e = 0; e < NE; e++) acc[e] = 0.0f;

    for (int k0 = 0; k0 < DIM; k0 += KC) {
        __syncthreads();   // previous chunk's compute done before overwrite

        // --- stage weight chunk transposed: ws[kk][e] = w[e][k0+kk] ---
        // NE*KC = 1024 floats, 128 threads -> 8 each
#pragma unroll
        for (int i = 0; i < (NE * KC) / TPC; i++) {
            int idx = tid + i * TPC;
            int e   = idx / KC;
            int kk  = idx - e * KC;
            ws[kk][e] = w[(size_t)e * DIM + k0 + kk];
        }

        // --- stage x chunk: 128 tokens x 16 k, float4 coalesced ---
        // TPC*KC/4 = 512 float4 loads, 128 threads -> 4 each
#pragma unroll
        for (int i = 0; i < (TPC * KC / 4) / TPC; i++) {
            int idx4 = tid + i * TPC;
            int tt   = idx4 / (KC / 4);
            int kk4  = idx4 - tt * (KC / 4);
            float4 v = *(const float4*)(x + (size_t)(t0 + tt) * DIM + k0 + kk4 * 4);
            *(float4*)&xs[tt][kk4 * 4] = v;
        }
        __syncthreads();

        // --- pull own token's x slice into registers ---
        float xr[KC];
#pragma unroll
        for (int i = 0; i < KC / 4; i++)
            ((float4*)xr)[i] = *(const float4*)&xs[tid][i * 4];

        // --- FMA core: 64 experts x KC ---
#pragma unroll
        for (int kk = 0; kk < KC; kk++) {
            float xv = xr[kk];
#pragma unroll
            for (int e4 = 0; e4 < NE / 4; e4++) {
                float4 wv = *(const float4*)&ws[kk][e4 * 4];   // broadcast LDS.128
                acc[e4 * 4 + 0] = fmaf(xv, wv.x, acc[e4 * 4 + 0]);
                acc[e4 * 4 + 1] = fmaf(xv, wv.y, acc[e4 * 4 + 1]);
                acc[e4 * 4 + 2] = fmaf(xv, wv.z, acc[e4 * 4 + 2]);
                acc[e4 * 4 + 3] = fmaf(xv, wv.w, acc[e4 * 4 + 3]);
            }
        }
    }

    // --- softmax over 64 logits (all in registers) ---
    float m = -CUDART_INF_F;
#pragma unroll
    for (int e = 0; e < NE; e++) m = fmaxf(m, acc[e]);
    float sum = 0.0f;
#pragma unroll
    for (int e = 0; e < NE; e++) { acc[e] = __expf(acc[e] - m); sum += acc[e]; }
    float inv = 1.0f / sum;
#pragma unroll
    for (int e = 0; e < NE; e++) acc[e] *= inv;

    // --- top-6 of (score + bias), output original score + index ---
    // strict '>' keeps the lowest index on ties, matching jax.lax.top_k.
    unsigned long long taken = 0ull;
    const int t = t0 + tid;
    float* wout = out + (size_t)t * TOPK;
    float* iout = out + (size_t)TOKENS * TOPK + (size_t)t * TOPK;

#pragma unroll
    for (int s = 0; s < TOPK; s++) {
        float best = -CUDART_INF_F;
        float bsc  = 0.0f;
        int   be   = 0;
#pragma unroll
        for (int e = 0; e < NE; e++) {
            float v  = acc[e] + bs[e];
            bool  ok = ((taken >> e) & 1ull) == 0ull;
            if (ok && v > best) { best = v; bsc = acc[e]; be = e; }
        }
        taken |= (1ull << be);
        wout[s] = bsc;          // ROUTE_SCALE == 1.0
        iout[s] = (float)be;    // indices emitted numerically in output dtype
    }
}

extern "C" void kernel_launch(void* const* d_in, const int* in_sizes, int n_in,
                              void* d_out, int out_size) {
    const float* x    = (const float*)d_in[0];
    const float* w    = (const float*)d_in[1];
    const float* bias = (const float*)d_in[2];
    float* out        = (float*)d_out;

    dim3 grid(TOKENS / TPC);   // 256 CTAs
    dim3 block(TPC);           // 128 threads
    gate_fused_kernel<<<grid, block>>>(x, w, bias, out);
}

// round 2
// speedup vs baseline: 1.5144x; 1.5144x over previous
#include <cuda_runtime.h>
#include <cuda_bf16.h>
#include <math_constants.h>

#define TOKENS  32768
#define DIM     2048
#define NE      64
#define TOPK    6

#define TPC     32      // tokens per CTA
#define NTH     32      // threads per CTA (single warp)
#define NP      16      // token pairs per CTA
#define EH      32      // experts per half-warp
#define KC      16      // K-chunk

#define XS_STRIDE 20    // KC + 4 pad (80B rows: 16B aligned, 2-way worst conflict)
#define WS_STRIDE 68    // row: experts 0-31 at col 0, experts 32-63 at col 36
#define WOFF      36    // upper-half column offset -> disjoint banks for the 2 bcast groups
#define LG_STRIDE 33    // TPC + 1 (conflict-free transposed epilogue reads)

// packed dual-FMA: per-half IEEE fp32 FMA, bitwise == scalar fmaf
__device__ __forceinline__ unsigned long long fma2(unsigned long long a,
                                                   unsigned long long b,
                                                   unsigned long long c) {
    unsigned long long d;
    asm("fma.rn.f32x2 %0, %1, %2, %3;" : "=l"(d) : "l"(a), "l"(b), "l"(c));
    return d;
}
__device__ __forceinline__ unsigned long long dupf32(float v) {
    unsigned long long d;
    asm("mov.b64 %0, {%1, %1};" : "=l"(d) : "f"(v));
    return d;
}
__device__ __forceinline__ void unpack2(unsigned long long v, float& lo, float& hi) {
    asm("mov.b64 {%0, %1}, %2;" : "=f"(lo), "=f"(hi) : "l"(v));
}

__global__ __launch_bounds__(NTH)
void gate_f32x2_kernel(const float* __restrict__ x,
                       const float* __restrict__ w,
                       const float* __restrict__ bias,
                       float* __restrict__ out) {
    __shared__ union {
        struct {
            float ws[KC][WS_STRIDE];    // transposed weight chunk
            float xs[TPC][XS_STRIDE];   // x chunk
        } mb;
        float logits[NE][LG_STRIDE];    // epilogue scratch (reuses mainloop smem)
    } sm;
    __shared__ float bs[NE];

    const int lane = threadIdx.x;
    const int p    = lane & (NP - 1);   // token pair 0..15
    const int h    = lane >> 4;         // expert half 0..1
    const int t0   = blockIdx.x * TPC;

    for (int e = lane; e < NE; e += NTH) bs[e] = bias[e];

    // accumulators: [token 0|1][expert pair], experts h*32 + 2q, 2q+1
    unsigned long long acc[2][EH / 2];
#pragma unroll
    for (int t = 0; t < 2; t++)
#pragma unroll
        for (int q = 0; q < EH / 2; q++) acc[t][q] = 0ull;

    // software-pipelined staging registers
    float4 wreg[8], xreg[4];

    // prologue: prefetch chunk 0
#pragma unroll
    for (int i = 0; i < 8; i++) {
        int idx4 = lane + i * NTH;          // 0..255 : 64 experts x 4 float4
        int e = idx4 >> 2, kk4 = idx4 & 3;
        wreg[i] = *(const float4*)(w + (size_t)e * DIM + kk4 * 4);
    }
#pragma unroll
    for (int i = 0; i < 4; i++) {
        int idx4 = lane + i * NTH;          // 0..127 : 32 tokens x 4 float4
        int tt = idx4 >> 2, kk4 = idx4 & 3;
        xreg[i] = *(const float4*)(x + (size_t)(t0 + tt) * DIM + kk4 * 4);
    }

    for (int k0 = 0; k0 < DIM; k0 += KC) {
        // ---- store prefetched chunk to smem ----
#pragma unroll
        for (int i = 0; i < 8; i++) {
            int idx4 = lane + i * NTH;
            int e = idx4 >> 2, kk4 = idx4 & 3;
            int col = (e < EH) ? e : (e + (WOFF - EH));
            sm.mb.ws[kk4 * 4 + 0][col] = wreg[i].x;
            sm.mb.ws[kk4 * 4 + 1][col] = wreg[i].y;
            sm.mb.ws[kk4 * 4 + 2][col] = wreg[i].z;
            sm.mb.ws[kk4 * 4 + 3][col] = wreg[i].w;
        }
#pragma unroll
        for (int i = 0; i < 4; i++) {
            int idx4 = lane + i * NTH;
            int tt = idx4 >> 2, kk4 = idx4 & 3;
            *(float4*)&sm.mb.xs[tt][kk4 * 4] = xreg[i];
        }
        __syncwarp();

        // ---- prefetch next chunk (overlaps with FMA block below) ----
        if (k0 + KC < DIM) {
            int kn = k0 + KC;
#pragma unroll
            for (int i = 0; i < 8; i++) {
                int idx4 = lane + i * NTH;
                int e = idx4 >> 2, kk4 = idx4 & 3;
                wreg[i] = *(const float4*)(w + (size_t)e * DIM + kn + kk4 * 4);
            }
#pragma unroll
            for (int i = 0; i < 4; i++) {
                int idx4 = lane + i * NTH;
                int tt = idx4 >> 2, kk4 = idx4 & 3;
                xreg[i] = *(const float4*)(x + (size_t)(t0 + tt) * DIM + kn + kk4 * 4);
            }
        }

        // ---- own tokens' x slice ----
        float xr0[KC], xr1[KC];
#pragma unroll
        for (int i = 0; i < KC / 4; i++) {
            ((float4*)xr0)[i] = *(const float4*)&sm.mb.xs[p][i * 4];
            ((float4*)xr1)[i] = *(const float4*)&sm.mb.xs[p + NP][i * 4];
        }

        // ---- FMA2 core: 16 kk x 16 expert-pairs x 2 tokens ----
#pragma unroll
        for (int kk = 0; kk < KC; kk++) {
            unsigned long long xp0 = dupf32(xr0[kk]);
            unsigned long long xp1 = dupf32(xr1[kk]);
            const float* wr = &sm.mb.ws[kk][h * WOFF];
#pragma unroll
            for (int q = 0; q < EH / 4; q++) {            // 8 iters, 2 pairs each
                ulonglong2 wv = *(const ulonglong2*)(wr + q * 4);  // bcast LDS.128
                acc[0][2 * q + 0] = fma2(wv.x, xp0, acc[0][2 * q + 0]);
                acc[0][2 * q + 1] = fma2(wv.y, xp0, acc[0][2 * q + 1]);
                acc[1][2 * q + 0] = fma2(wv.x, xp1, acc[1][2 * q + 0]);
                acc[1][2 * q + 1] = fma2(wv.y, xp1, acc[1][2 * q + 1]);
            }
        }
        __syncwarp();   // compute done before next iter's STS overwrites
    }

    // ---- scatter logits to transposed smem ----
#pragma unroll
    for (int q = 0; q < EH / 2; q++) {
        float a, b, c, d;
        unpack2(acc[0][q], a, b);
        unpack2(acc[1][q], c, d);
        sm.logits[h * EH + 2 * q + 0][p]      = a;
        sm.logits[h * EH + 2 * q + 1][p]      = b;
        sm.logits[h * EH + 2 * q + 0][p + NP] = c;
        sm.logits[h * EH + 2 * q + 1][p + NP] = d;
    }
    __syncwarp();

    // ---- per-thread token: softmax + bias-shifted top-6 ----
    float s[NE];
#pragma unroll
    for (int e = 0; e < NE; e++) s[e] = sm.logits[e][lane];

    float m = -CUDART_INF_F;
#pragma unroll
    for (int e = 0; e < NE; e++) m = fmaxf(m, s[e]);
    float sum = 0.0f;
#pragma unroll
    for (int e = 0; e < NE; e++) { s[e] = __expf(s[e] - m); sum += s[e]; }
    float inv = 1.0f / sum;
#pragma unroll
    for (int e = 0; e < NE; e++) s[e] *= inv;

    unsigned long long taken = 0ull;
    const int t = t0 + lane;
    float* wout = out + (size_t)t * TOPK;
    float* iout = out + (size_t)TOKENS * TOPK + (size_t)t * TOPK;

#pragma unroll
    for (int sidx = 0; sidx < TOPK; sidx++) {
        float best = -CUDART_INF_F;
        float bsc  = 0.0f;
        int   be   = 0;
#pragma unroll
        for (int e = 0; e < NE; e++) {
            float v  = s[e] + bs[e];                 // bcast LDS
            bool  ok = ((taken >> e) & 1ull) == 0ull;
            if (ok && v > best) { best = v; bsc = s[e]; be = e; }
        }
        taken |= (1ull << be);
        wout[sidx] = bsc;        // ROUTE_SCALE == 1.0
        iout[sidx] = (float)be;
    }
}

extern "C" void kernel_launch(void* const* d_in, const int* in_sizes, int n_in,
                              void* d_out, int out_size) {
    const float* x    = (const float*)d_in[0];
    const float* w    = (const float*)d_in[1];
    const float* bias = (const float*)d_in[2];
    float* out        = (float*)d_out;

    gate_f32x2_kernel<<<TOKENS / TPC, NTH>>>(x, w, bias, out);
}

// round 3
// speedup vs baseline: 1.8931x; 1.2500x over previous
#include <cuda_runtime.h>
#include <cuda_bf16.h>
#include <math_constants.h>

#define TOKENS  32768
#define DIM     2048
#define NE      64
#define TOPK    6

#define NTH     64          // 2 warps per CTA
#define TPC     32          // tokens per CTA
#define KHALF   (DIM / 2)   // K range per warp
#define KC      8           // K per chunk
#define NCHUNK  (KHALF / KC)    // 128

#define WSROW   80          // smem/scratch weight row stride (floats)
#define XSROW   12          // smem x row stride (floats)
#define LGROW   33          // logits row stride

typedef unsigned long long ull;

// packed dual fp32 FMA (per-half IEEE, bitwise == 2x fmaf)
__device__ __forceinline__ ull fma2(ull a, ull b, ull c) {
    ull d; asm("fma.rn.f32x2 %0, %1, %2, %3;" : "=l"(d) : "l"(a), "l"(b), "l"(c)); return d;
}
__device__ __forceinline__ ull dupf(float v) {
    ull d; asm("mov.b64 %0, {%1, %1};" : "=l"(d) : "f"(v)); return d;
}
__device__ __forceinline__ void unpack2(ull v, float& lo, float& hi) {
    asm("mov.b64 {%0, %1}, %2;" : "=f"(lo), "=f"(hi) : "l"(v));
}
__device__ __forceinline__ unsigned smem_u32(const void* p) {
    return (unsigned)__cvta_generic_to_shared(p);
}
__device__ __forceinline__ void cp16(unsigned dst, const void* src) {
    asm volatile("cp.async.cg.shared.global [%0], [%1], 16;" :: "r"(dst), "l"(src));
}

// Pre-transposed weights in the exact smem tile layout:
// row k, expert e at col (e>>4)*20 + (e&15); cols 16..19 of each window are pad.
__device__ float g_wT[DIM * WSROW];

__global__ void transpose_w_kernel(const float* __restrict__ w) {
    int idx = blockIdx.x * 256 + threadIdx.x;      // < DIM*WSROW
    int k = idx / WSROW, c = idx - k * WSROW;
    int g = c / 20, j = c - g * 20;
    float v = 0.0f;
    if (j < 16) v = w[(size_t)(g * 16 + j) * DIM + k];
    g_wT[idx] = v;
}

__global__ __launch_bounds__(NTH, 7)
void gate_ksplit_kernel(const float* __restrict__ x,
                        const float* __restrict__ bias,
                        float* __restrict__ out) {
    __shared__ union {
        struct {
            float ws[2][2][KC][WSROW];    // [warp][buf]
            float xs[2][2][TPC][XSROW];   // [warp][buf]
        } mb;
        float lg[2][NE][LGROW];           // epilogue partial logits per warp
    } sm;
    __shared__ float bs[NE];

    const int tid  = threadIdx.x;
    const int wid  = tid >> 5;
    const int lane = tid & 31;
    const int egrp = lane >> 3;          // 0..3 -> experts [16*egrp, 16*egrp+16)
    const int slot = lane & 7;           // tokens {slot, slot+8, slot+16, slot+24}
    const int t0   = blockIdx.x * TPC;
    const int kbase = wid * KHALF;

    bs[tid & (NE - 1)] = bias[tid & (NE - 1)];

    // ---- cp.async staging setup (per lane: 5 weight chunks + 2 x chunks of 16B) ----
    const float* wsrc[5]; unsigned wdst[5];
#pragma unroll
    for (int i = 0; i < 5; i++) {
        int id = lane + 32 * i;              // 0..159 over 8 rows x 20 16B-chunks
        int r = id / 20, cc = id - r * 20;
        wsrc[i] = g_wT + (size_t)(kbase + r) * WSROW + cc * 4;
        wdst[i] = smem_u32(&sm.mb.ws[wid][0][r][cc * 4]);
    }
    const float* xsrc[2]; unsigned xdst[2];
#pragma unroll
    for (int i = 0; i < 2; i++) {
        int id = lane + 32 * i;              // 0..63 over 32 rows x 2 16B-chunks
        int r = id >> 1, cc = id & 1;
        xsrc[i] = x + (size_t)(t0 + r) * DIM + kbase + cc * 4;
        xdst[i] = smem_u32(&sm.mb.xs[wid][0][r][cc * 4]);
    }
    const unsigned WSB = KC * WSROW * 4;     // buf stride bytes (weights)
    const unsigned XSB = TPC * XSROW * 4;    // buf stride bytes (x)

    ull acc[4][8];                           // [token][expert pair]
#pragma unroll
    for (int t = 0; t < 4; t++)
#pragma unroll
        for (int j = 0; j < 8; j++) acc[t][j] = 0ull;

    // prologue: chunk 0 -> buf 0
#pragma unroll
    for (int i = 0; i < 5; i++) { cp16(wdst[i], wsrc[i]); wsrc[i] += KC * WSROW; }
#pragma unroll
    for (int i = 0; i < 2; i++) { cp16(xdst[i], xsrc[i]); xsrc[i] += KC; }
    asm volatile("cp.async.commit_group;");

    unsigned buf = 0;
    for (int c = 0; c < NCHUNK; c++) {
        if (c + 1 < NCHUNK) {
            unsigned ob = buf ^ 1;
#pragma unroll
            for (int i = 0; i < 5; i++) { cp16(wdst[i] + ob * WSB, wsrc[i]); wsrc[i] += KC * WSROW; }
#pragma unroll
            for (int i = 0; i < 2; i++) { cp16(xdst[i] + ob * XSB, xsrc[i]); xsrc[i] += KC; }
            asm volatile("cp.async.commit_group;");
            asm volatile("cp.async.wait_group 1;");
        } else {
            asm volatile("cp.async.wait_group 0;");
        }
        __syncwarp();

        const float (*wsb)[WSROW] = sm.mb.ws[wid][buf];
        const float (*xsb)[XSROW] = sm.mb.xs[wid][buf];

#pragma unroll
        for (int kh = 0; kh < 2; kh++) {
            float4 xv[4];
#pragma unroll
            for (int t = 0; t < 4; t++)
                xv[t] = *(const float4*)&xsb[slot + 8 * t][kh * 4];
#pragma unroll
            for (int kk = 0; kk < 4; kk++) {
                ull xp[4];
#pragma unroll
                for (int t = 0; t < 4; t++) {
                    float xe = (kk == 0) ? xv[t].x : (kk == 1) ? xv[t].y
                             : (kk == 2) ? xv[t].z : xv[t].w;
                    xp[t] = dupf(xe);
                }
                const float* wr = &wsb[kh * 4 + kk][egrp * 20];
#pragma unroll
                for (int q = 0; q < 4; q++) {
                    ulonglong2 wv = *(const ulonglong2*)(wr + q * 4);  // bcast LDS.128
#pragma unroll
                    for (int t = 0; t < 4; t++) {
                        acc[t][2 * q + 0] = fma2(wv.x, xp[t], acc[t][2 * q + 0]);
                        acc[t][2 * q + 1] = fma2(wv.y, xp[t], acc[t][2 * q + 1]);
                    }
                }
            }
        }
        buf ^= 1;
        __syncwarp();   // all lanes done reading before next chunk's cp.async overwrites
    }

    // ---- reduce K-split partials via smem (union overlays mainloop buffers) ----
    __syncthreads();    // both warps out of mainloop before clobbering the union
#pragma unroll
    for (int t = 0; t < 4; t++) {
        int tk = slot + 8 * t;
#pragma unroll
        for (int j = 0; j < 8; j++) {
            float lo, hi; unpack2(acc[t][j], lo, hi);
            int e = 16 * egrp + 2 * j;
            sm.lg[wid][e][tk]     = lo;
            sm.lg[wid][e + 1][tk] = hi;
        }
    }
    __syncthreads();

    if (tid < TPC) {
        float s[NE];
#pragma unroll
        for (int e = 0; e < NE; e++) s[e] = sm.lg[0][e][tid] + sm.lg[1][e][tid];

        float m = -CUDART_INF_F;
#pragma unroll
        for (int e = 0; e < NE; e++) m = fmaxf(m, s[e]);
        float sum = 0.0f;
#pragma unroll
        for (int e = 0; e < NE; e++) { s[e] = __expf(s[e] - m); sum += s[e]; }
        float inv = 1.0f / sum;
#pragma unroll
        for (int e = 0; e < NE; e++) s[e] *= inv;

        unsigned long long taken = 0ull;
        const int t = t0 + tid;
        float* wout = out + (size_t)t * TOPK;
        float* iout = out + (size_t)TOKENS * TOPK + (size_t)t * TOPK;

#pragma unroll
        for (int sidx = 0; sidx < TOPK; sidx++) {
            float best = -CUDART_INF_F;
            float bsc  = 0.0f;
            int   be   = 0;
#pragma unroll
            for (int e = 0; e < NE; e++) {
                float v  = s[e] + bs[e];
                bool  ok = ((taken >> e) & 1ull) == 0ull;
                if (ok && v > best) { best = v; bsc = s[e]; be = e; }
            }
            taken |= (1ull << be);
            wout[sidx] = bsc;        // ROUTE_SCALE == 1.0
            iout[sidx] = (float)be;
        }
    }
}

extern "C" void kernel_launch(void* const* d_in, const int* in_sizes, int n_in,
                              void* d_out, int out_size) {
    const float* x    = (const float*)d_in[0];
    const float* w    = (const float*)d_in[1];
    const float* bias = (const float*)d_in[2];
    float* out        = (float*)d_out;

    transpose_w_kernel<<<(DIM * WSROW) / 256, 256>>>(w);
    gate_ksplit_kernel<<<TOKENS / TPC, NTH>>>(x, bias, out);
}

// round 6
// speedup vs baseline: 2.6162x; 1.3820x over previous
#include <cuda_runtime.h>
#include <cuda_bf16.h>
#include <math_constants.h>
#include <cstdint>

#define TOKENS  32768
#define DIM     2048
#define NE      64
#define TOPK    6
#define MT      128                 // tokens per CTA
#define KCH     32                  // K per chunk
#define NCH     (DIM / KCH)         // 64
#define NTH     256

// smem map (dynamic): x 2x16KB | w 2x12KB | bias
#define OFFX    0
#define OFFW    32768
#define OFFB    57344
#define SMEMSZ  57600

// pre-split, pre-swizzled bf16 weights: [term][chunk][64 experts x 64B]
__device__ __align__(16) unsigned char g_wsw[3][NCH][NE * KCH * 2];

__device__ __forceinline__ unsigned su32(const void* p) {
    return (unsigned)__cvta_generic_to_shared(p);
}
__device__ __forceinline__ void cp16(unsigned d, const void* s) {
    asm volatile("cp.async.cg.shared.global [%0], [%1], 16;" :: "r"(d), "l"(s));
}
// split (f0,f1) -> three packed bf16x2 (lo half = f0 term)
__device__ __forceinline__ void split2(float f0, float f1,
                                       unsigned& p1, unsigned& p2, unsigned& p3) {
    asm("cvt.rn.bf16x2.f32 %0, %1, %2;" : "=r"(p1) : "f"(f1), "f"(f0));
    float g0 = __uint_as_float(p1 << 16);
    float g1 = __uint_as_float(p1 & 0xFFFF0000u);
    float r0 = f0 - g0, r1 = f1 - g1;
    asm("cvt.rn.bf16x2.f32 %0, %1, %2;" : "=r"(p2) : "f"(r1), "f"(r0));
    float h0 = __uint_as_float(p2 << 16);
    float h1 = __uint_as_float(p2 & 0xFFFF0000u);
    float s0 = r0 - h0, s1 = r1 - h1;
    asm("cvt.rn.bf16x2.f32 %0, %1, %2;" : "=r"(p3) : "f"(s1), "f"(s0));
}
__device__ __forceinline__ void ldsm4(unsigned b[4], unsigned addr) {
    asm volatile("ldmatrix.sync.aligned.m8n8.x4.shared.b16 {%0,%1,%2,%3}, [%4];"
                 : "=r"(b[0]), "=r"(b[1]), "=r"(b[2]), "=r"(b[3]) : "r"(addr));
}
// accumulate form: C += A*B (in-tensor-core chain, used only within a k-step)
__device__ __forceinline__ void mma16816(float* c, const unsigned* a,
                                         unsigned b0, unsigned b1) {
    asm volatile(
        "mma.sync.aligned.m16n8k16.row.col.f32.bf16.bf16.f32 "
        "{%0,%1,%2,%3}, {%4,%5,%6,%7}, {%8,%9}, {%0,%1,%2,%3};"
        : "+f"(c[0]), "+f"(c[1]), "+f"(c[2]), "+f"(c[3])
        : "r"(a[0]), "r"(a[1]), "r"(a[2]), "r"(a[3]), "r"(b0), "r"(b1));
}
// zero-start form: C = A*B + 0 (resets the accumulation chain each k-step)
__device__ __forceinline__ void mma16816_z(float* c, const unsigned* a,
                                           unsigned b0, unsigned b1) {
    asm volatile(
        "mma.sync.aligned.m16n8k16.row.col.f32.bf16.bf16.f32 "
        "{%0,%1,%2,%3}, {%4,%5,%6,%7}, {%8,%9}, {%10,%11,%12,%13};"
        : "=f"(c[0]), "=f"(c[1]), "=f"(c[2]), "=f"(c[3])
        : "r"(a[0]), "r"(a[1]), "r"(a[2]), "r"(a[3]), "r"(b0), "r"(b1),
          "f"(0.0f), "f"(0.0f), "f"(0.0f), "f"(0.0f));
}

// ---- pre-kernel: 3-term bf16 split of w, ldmatrix-swizzled rows of 64B ----
__global__ void split_w_kernel(const float* __restrict__ w) {
    int idx = blockIdx.x * 256 + threadIdx.x;     // e*DIM + k, < 131072
    int e = idx >> 11, k = idx & (DIM - 1);
    float v = w[idx];
    __nv_bfloat16 b1 = __float2bfloat16(v);
    float f1 = __uint_as_float(((unsigned)*(unsigned short*)&b1) << 16);
    float r1 = v - f1;
    __nv_bfloat16 b2 = __float2bfloat16(r1);
    float f2 = __uint_as_float(((unsigned)*(unsigned short*)&b2) << 16);
    __nv_bfloat16 b3 = __float2bfloat16(r1 - f2);
    int c = k >> 5, kk = k & (KCH - 1);
    unsigned off = ((unsigned)e << 6) | ((unsigned)kk << 1);
    unsigned sw = off ^ (((off >> 7) & 3u) << 4);   // bits[5:4] ^= bits[8:7]
    *(unsigned short*)&g_wsw[0][c][sw] = *(unsigned short*)&b1;
    *(unsigned short*)&g_wsw[1][c][sw] = *(unsigned short*)&b2;
    *(unsigned short*)&g_wsw[2][c][sw] = *(unsigned short*)&b3;
}

__global__ __launch_bounds__(NTH, 2)
void gate_hmma_kernel(const float* __restrict__ x,
                      const float* __restrict__ bias,
                      float* __restrict__ out) {
    extern __shared__ unsigned char sm[];

    const int tid = threadIdx.x;
    const int wid = tid >> 5;
    const int L   = tid & 31;
    const int r4  = L >> 2;          // 0..7
    const int cq  = L & 3;           // 0..3
    const int t0  = blockIdx.x * MT;

    if (tid < NE) ((float*)(sm + OFFB))[tid] = bias[tid];

    // ---- cp.async source/dest setup ----
    const float* xsrc[4]; unsigned xdst[4];
#pragma unroll
    for (int i = 0; i < 4; i++) {
        int u = tid + NTH * i;               // 0..1023 = 128 tokens x 8 16B units
        int tt = u >> 3, q = u & 7;
        xsrc[i] = x + (size_t)(t0 + tt) * DIM + q * 4;
        unsigned off = ((unsigned)tt << 7) | ((unsigned)q << 4);
        xdst[i] = su32(sm + OFFX) + (off ^ ((off >> 3) & 0x70u));
    }
    const unsigned char* wsrc[3]; unsigned wdst[3];
#pragma unroll
    for (int i = 0; i < 3; i++) {
        int u = tid + NTH * i;               // 0..767 = 3 terms x 256 units
        int trm = u >> 8; unsigned o = (unsigned)(u & 255) << 4;
        wsrc[i] = &g_wsw[trm][0][o];
        wdst[i] = su32(sm + OFFW) + trm * 4096 + o;
    }

    // fp32 running logits (IEEE adds), drained from short tensor-core chains
    float run[8][4];
#pragma unroll
    for (int n = 0; n < 8; n++)
#pragma unroll
        for (int i = 0; i < 4; i++) run[n][i] = 0.0f;

    // prologue: chunk 0 -> buf 0
#pragma unroll
    for (int i = 0; i < 4; i++) { cp16(xdst[i], xsrc[i]); xsrc[i] += KCH; }
#pragma unroll
    for (int i = 0; i < 3; i++) { cp16(wdst[i], wsrc[i]); wsrc[i] += 4096; }
    asm volatile("cp.async.commit_group;");

    unsigned buf = 0;
    const int R0 = wid * 16 + r4;           // thread's token rows R0, R0+8

    for (int ch = 0; ch < NCH; ch++) {
        if (ch + 1 < NCH) {
            unsigned ob = buf ^ 1;
#pragma unroll
            for (int i = 0; i < 4; i++) { cp16(xdst[i] + ob * 16384, xsrc[i]); xsrc[i] += KCH; }
#pragma unroll
            for (int i = 0; i < 3; i++) { cp16(wdst[i] + ob * 12288, wsrc[i]); wsrc[i] += 4096; }
            asm volatile("cp.async.commit_group;");
            asm volatile("cp.async.wait_group 1;");
        } else {
            asm volatile("cp.async.wait_group 0;");
        }
        __syncthreads();

        const unsigned xb = su32(sm + OFFX) + buf * 16384;
        const unsigned wb = su32(sm + OFFW) + buf * 12288;

#pragma unroll
        for (int s = 0; s < 2; s++) {       // two k16 steps per chunk
            // ---- A fragments: LDS pairs + 3-way split ----
            unsigned a[3][4];
#pragma unroll
            for (int half = 0; half < 2; half++) {
#pragma unroll
                for (int rowi = 0; rowi < 2; rowi++) {
                    int row = R0 + rowi * 8;
                    unsigned off = ((unsigned)row << 7)
                                 + ((unsigned)(s * 16 + cq * 2 + half * 8) << 2);
                    unsigned sw = off ^ ((off >> 3) & 0x70u);
                    float f0, f1;
                    asm volatile("ld.shared.v2.f32 {%0,%1}, [%2];"
                                 : "=f"(f0), "=f"(f1) : "r"(xb + sw));
                    int pi = half * 2 + rowi;   // a0,a1,a2,a3 order
                    split2(f0, f1, a[0][pi], a[1][pi], a[2][pi]);
                }
            }
            // ---- B terms + HMMA (short chains: 6 MMAs per C per k-step) ----
            float c[8][4];
            const int m  = L >> 3;          // ldmatrix matrix id
            const int rr = L & 7;
#pragma unroll
            for (int tb = 0; tb < 3; tb++) {
                const int nta = 3 - tb;     // a-terms paired with this b-term
#pragma unroll
                for (int p = 0; p < 4; p++) {
                    int e = p * 16 + (m >> 1) * 8 + rr;
                    unsigned off = ((unsigned)e << 6) + s * 32 + (m & 1) * 16;
                    unsigned sw = off ^ (((off >> 7) & 3u) << 4);
                    unsigned br[4];
                    ldsm4(br, wb + tb * 4096 + sw);
#pragma unroll
                    for (int ta = 0; ta < nta; ta++) {
                        if (tb == 0 && ta == 0) {
                            mma16816_z(c[2 * p + 0], a[0], br[0], br[1]);
                            mma16816_z(c[2 * p + 1], a[0], br[2], br[3]);
                        } else {
                            mma16816(c[2 * p + 0], a[ta], br[0], br[1]);
                            mma16816(c[2 * p + 1], a[ta], br[2], br[3]);
                        }
                    }
                }
            }
            // ---- drain: IEEE fp32 adds into running logits ----
#pragma unroll
            for (int nt = 0; nt < 8; nt++)
#pragma unroll
                for (int i = 0; i < 4; i++) run[nt][i] += c[nt][i];
        }
        __syncthreads();
        buf ^= 1;
    }

    // ---- scatter logits to smem [128][65] (overlays mainloop buffers) ----
    float* lg = (float*)sm;
#pragma unroll
    for (int nt = 0; nt < 8; nt++)
#pragma unroll
        for (int i = 0; i < 4; i++) {
            int tk = R0 + ((i >= 2) ? 8 : 0);         // c0,c1 row; c2,c3 row+8
            int ex = nt * 8 + cq * 2 + (i & 1);
            lg[tk * 65 + ex] = run[nt][i];
        }
    __syncthreads();

    if (tid < MT) {
        float sc[NE];
#pragma unroll
        for (int e = 0; e < NE; e++) sc[e] = lg[tid * 65 + e];

        float mx = -CUDART_INF_F;
#pragma unroll
        for (int e = 0; e < NE; e++) mx = fmaxf(mx, sc[e]);
        float sum = 0.0f;
#pragma unroll
        for (int e = 0; e < NE; e++) { sc[e] = __expf(sc[e] - mx); sum += sc[e]; }
        float inv = 1.0f / sum;
#pragma unroll
        for (int e = 0; e < NE; e++) sc[e] *= inv;

        const float* bs = (const float*)(sm + OFFB);
        unsigned long long taken = 0ull;
        const int t = t0 + tid;
        float* wout = out + (size_t)t * TOPK;
        float* iout = out + (size_t)TOKENS * TOPK + (size_t)t * TOPK;

#pragma unroll
        for (int sidx = 0; sidx < TOPK; sidx++) {
            float best = -CUDART_INF_F;
            float bsc = 0.0f;
            int be = 0;
#pragma unroll
            for (int e = 0; e < NE; e++) {
                float v = sc[e] + bs[e];
                bool ok = ((taken >> e) & 1ull) == 0ull;
                if (ok && v > best) { best = v; bsc = sc[e]; be = e; }
            }
            taken |= (1ull << be);
            wout[sidx] = bsc;        // ROUTE_SCALE == 1.0
            iout[sidx] = (float)be;
        }
    }
}

extern "C" void kernel_launch(void* const* d_in, const int* in_sizes, int n_in,
                              void* d_out, int out_size) {
    const float* x    = (const float*)d_in[0];
    const float* w    = (const float*)d_in[1];
    const float* bias = (const float*)d_in[2];
    float* out        = (float*)d_out;

    cudaFuncSetAttribute(gate_hmma_kernel,
                         cudaFuncAttributeMaxDynamicSharedMemorySize, SMEMSZ);

    split_w_kernel<<<(NE * DIM) / 256, 256>>>(w);
    gate_hmma_kernel<<<TOKENS / MT, NTH, SMEMSZ>>>(x, bias, out);
}

// round 7
// speedup vs baseline: 2.9497x; 1.1275x over previous
#include <cuda_runtime.h>
#include <cuda_bf16.h>
#include <math_constants.h>
#include <cstdint>

#define TOKENS  32768
#define DIM     2048
#define NE      64
#define TOPK    6
#define MT      128                 // tokens per CTA
#define KCH     32                  // K per chunk
#define NCH     (DIM / KCH)         // 64
#define NTH     256

// smem map (dynamic): x 3x16KB | w 3x12KB | bias
#define OFFX    0
#define XBUF    16384
#define OFFW    49152
#define WBUF    12288
#define OFFB    86016
#define SMEMSZ  86272

// pre-split, pre-swizzled bf16 weights: [term][chunk][64 experts x 64B]
__device__ __align__(16) unsigned char g_wsw[3][NCH][NE * KCH * 2];

__device__ __forceinline__ unsigned su32(const void* p) {
    return (unsigned)__cvta_generic_to_shared(p);
}
__device__ __forceinline__ void cp16(unsigned d, const void* s) {
    asm volatile("cp.async.cg.shared.global [%0], [%1], 16;" :: "r"(d), "l"(s));
}
// split (f0,f1) -> three packed bf16x2 (lo half = f0 term)
__device__ __forceinline__ void split2(float f0, float f1,
                                       unsigned& p1, unsigned& p2, unsigned& p3) {
    asm("cvt.rn.bf16x2.f32 %0, %1, %2;" : "=r"(p1) : "f"(f1), "f"(f0));
    float g0 = __uint_as_float(p1 << 16);
    float g1 = __uint_as_float(p1 & 0xFFFF0000u);
    float r0 = f0 - g0, r1 = f1 - g1;
    asm("cvt.rn.bf16x2.f32 %0, %1, %2;" : "=r"(p2) : "f"(r1), "f"(r0));
    float h0 = __uint_as_float(p2 << 16);
    float h1 = __uint_as_float(p2 & 0xFFFF0000u);
    float s0 = r0 - h0, s1 = r1 - h1;
    asm("cvt.rn.bf16x2.f32 %0, %1, %2;" : "=r"(p3) : "f"(s1), "f"(s0));
}
__device__ __forceinline__ void ldsm4(unsigned b[4], unsigned addr) {
    asm volatile("ldmatrix.sync.aligned.m8n8.x4.shared.b16 {%0,%1,%2,%3}, [%4];"
                 : "=r"(b[0]), "=r"(b[1]), "=r"(b[2]), "=r"(b[3]) : "r"(addr));
}
// accumulate form: C += A*B (in-tensor-core chain within one chunk)
__device__ __forceinline__ void mma16816(float* c, const unsigned* a,
                                         unsigned b0, unsigned b1) {
    asm volatile(
        "mma.sync.aligned.m16n8k16.row.col.f32.bf16.bf16.f32 "
        "{%0,%1,%2,%3}, {%4,%5,%6,%7}, {%8,%9}, {%0,%1,%2,%3};"
        : "+f"(c[0]), "+f"(c[1]), "+f"(c[2]), "+f"(c[3])
        : "r"(a[0]), "r"(a[1]), "r"(a[2]), "r"(a[3]), "r"(b0), "r"(b1));
}
// zero-start form: C = A*B + 0 (resets the chunk-local chain)
__device__ __forceinline__ void mma16816_z(float* c, const unsigned* a,
                                           unsigned b0, unsigned b1) {
    asm volatile(
        "mma.sync.aligned.m16n8k16.row.col.f32.bf16.bf16.f32 "
        "{%0,%1,%2,%3}, {%4,%5,%6,%7}, {%8,%9}, {%10,%11,%12,%13};"
        : "=f"(c[0]), "=f"(c[1]), "=f"(c[2]), "=f"(c[3])
        : "r"(a[0]), "r"(a[1]), "r"(a[2]), "r"(a[3]), "r"(b0), "r"(b1),
          "f"(0.0f), "f"(0.0f), "f"(0.0f), "f"(0.0f));
}

// ---- pre-kernel: 3-term bf16 split of w, ldmatrix-swizzled rows of 64B ----
__global__ void split_w_kernel(const float* __restrict__ w) {
    int idx = blockIdx.x * 256 + threadIdx.x;     // e*DIM + k, < 131072
    int e = idx >> 11, k = idx & (DIM - 1);
    float v = w[idx];
    __nv_bfloat16 b1 = __float2bfloat16(v);
    float f1 = __uint_as_float(((unsigned)*(unsigned short*)&b1) << 16);
    float r1 = v - f1;
    __nv_bfloat16 b2 = __float2bfloat16(r1);
    float f2 = __uint_as_float(((unsigned)*(unsigned short*)&b2) << 16);
    __nv_bfloat16 b3 = __float2bfloat16(r1 - f2);
    int c = k >> 5, kk = k & (KCH - 1);
    unsigned off = ((unsigned)e << 6) | ((unsigned)kk << 1);
    unsigned sw = off ^ (((off >> 7) & 3u) << 4);   // bits[5:4] ^= bits[8:7]
    *(unsigned short*)&g_wsw[0][c][sw] = *(unsigned short*)&b1;
    *(unsigned short*)&g_wsw[1][c][sw] = *(unsigned short*)&b2;
    *(unsigned short*)&g_wsw[2][c][sw] = *(unsigned short*)&b3;
}

__global__ __launch_bounds__(NTH, 2)
void gate_hmma_kernel(const float* __restrict__ x,
                      const float* __restrict__ bias,
                      float* __restrict__ out) {
    extern __shared__ unsigned char sm[];

    const int tid = threadIdx.x;
    const int wid = tid >> 5;
    const int L   = tid & 31;
    const int r4  = L >> 2;          // 0..7
    const int cq  = L & 3;           // 0..3
    const int t0  = blockIdx.x * MT;

    if (tid < NE) ((float*)(sm + OFFB))[tid] = bias[tid];

    // ---- cp.async source/dest setup (slot-0 bases) ----
    const float* xsrc[4]; unsigned xdst[4];
#pragma unroll
    for (int i = 0; i < 4; i++) {
        int u = tid + NTH * i;               // 0..1023 = 128 tokens x 8 16B units
        int tt = u >> 3, q = u & 7;
        xsrc[i] = x + (size_t)(t0 + tt) * DIM + q * 4;
        unsigned off = ((unsigned)tt << 7) | ((unsigned)q << 4);
        xdst[i] = su32(sm + OFFX) + (off ^ ((off >> 3) & 0x70u));
    }
    const unsigned char* wsrc[3]; unsigned wdst[3];
#pragma unroll
    for (int i = 0; i < 3; i++) {
        int u = tid + NTH * i;               // 0..767 = 3 terms x 256 units
        int trm = u >> 8; unsigned o = (unsigned)(u & 255) << 4;
        wsrc[i] = &g_wsw[trm][0][o];
        wdst[i] = su32(sm + OFFW) + trm * 4096 + o;
    }

    // fp32 running logits (IEEE adds), drained once per chunk
    float run[8][4];
#pragma unroll
    for (int n = 0; n < 8; n++)
#pragma unroll
        for (int i = 0; i < 4; i++) run[n][i] = 0.0f;

    // prologue: chunks 0 and 1 -> slots 0 and 1
#pragma unroll
    for (int sl = 0; sl < 2; sl++) {
#pragma unroll
        for (int i = 0; i < 4; i++) { cp16(xdst[i] + sl * XBUF, xsrc[i]); xsrc[i] += KCH; }
#pragma unroll
        for (int i = 0; i < 3; i++) { cp16(wdst[i] + sl * WBUF, wsrc[i]); wsrc[i] += 4096; }
        asm volatile("cp.async.commit_group;");
    }

    const int R0 = wid * 16 + r4;           // thread's token rows R0, R0+8
    int slot = 0, pf = 2;

    for (int ch = 0; ch < NCH; ch++) {
        if (ch < NCH - 1) {
            asm volatile("cp.async.wait_group 1;");
        } else {
            asm volatile("cp.async.wait_group 0;");
        }
        __syncthreads();   // chunk ch visible to all; all done reading slot pf

        // prefetch chunk ch+2 into slot pf (the slot read at chunk ch-1)
        if (ch + 2 < NCH) {
#pragma unroll
            for (int i = 0; i < 4; i++) { cp16(xdst[i] + pf * XBUF, xsrc[i]); xsrc[i] += KCH; }
#pragma unroll
            for (int i = 0; i < 3; i++) { cp16(wdst[i] + pf * WBUF, wsrc[i]); wsrc[i] += 4096; }
            asm volatile("cp.async.commit_group;");
        }

        const unsigned xb = su32(sm + OFFX) + slot * XBUF;
        const unsigned wb = su32(sm + OFFW) + slot * WBUF;

        float cc[8][4];                     // chunk-local tensor-core chains
#pragma unroll
        for (int s = 0; s < 2; s++) {       // two k16 steps per chunk
            // ---- A fragments: LDS pairs + 3-way split ----
            unsigned a[3][4];
#pragma unroll
            for (int half = 0; half < 2; half++) {
#pragma unroll
                for (int rowi = 0; rowi < 2; rowi++) {
                    int row = R0 + rowi * 8;
                    unsigned off = ((unsigned)row << 7)
                                 + ((unsigned)(s * 16 + cq * 2 + half * 8) << 2);
                    unsigned sw = off ^ ((off >> 3) & 0x70u);
                    float f0, f1;
                    asm volatile("ld.shared.v2.f32 {%0,%1}, [%2];"
                                 : "=f"(f0), "=f"(f1) : "r"(xb + sw));
                    int pi = half * 2 + rowi;   // a0,a1,a2,a3 order
                    split2(f0, f1, a[0][pi], a[1][pi], a[2][pi]);
                }
            }
            // ---- B terms + HMMA (12-MMA chunk-local chains) ----
            const int m  = L >> 3;          // ldmatrix matrix id
            const int rr = L & 7;
#pragma unroll
            for (int tb = 0; tb < 3; tb++) {
                const int nta = 3 - tb;     // a-terms paired with this b-term
#pragma unroll
                for (int p = 0; p < 4; p++) {
                    int e = p * 16 + (m >> 1) * 8 + rr;
                    unsigned off = ((unsigned)e << 6) + s * 32 + (m & 1) * 16;
                    unsigned sw = off ^ (((off >> 7) & 3u) << 4);
                    unsigned br[4];
                    ldsm4(br, wb + tb * 4096 + sw);
#pragma unroll
                    for (int ta = 0; ta < nta; ta++) {
                        if (s == 0 && tb == 0 && ta == 0) {
                            mma16816_z(cc[2 * p + 0], a[0], br[0], br[1]);
                            mma16816_z(cc[2 * p + 1], a[0], br[2], br[3]);
                        } else {
                            mma16816(cc[2 * p + 0], a[ta], br[0], br[1]);
                            mma16816(cc[2 * p + 1], a[ta], br[2], br[3]);
                        }
                    }
                }
            }
        }
        // ---- drain once per chunk: IEEE fp32 adds ----
#pragma unroll
        for (int nt = 0; nt < 8; nt++)
#pragma unroll
            for (int i = 0; i < 4; i++) run[nt][i] += cc[nt][i];

        slot = (slot == 2) ? 0 : slot + 1;
        pf   = (pf   == 2) ? 0 : pf   + 1;
    }

    __syncthreads();   // all warps done with mainloop buffers before overlay

    // ---- scatter logits to smem [128][65] (overlays mainloop buffers) ----
    float* lg = (float*)sm;
#pragma unroll
    for (int nt = 0; nt < 8; nt++)
#pragma unroll
        for (int i = 0; i < 4; i++) {
            int tk = R0 + ((i >= 2) ? 8 : 0);         // c0,c1 row; c2,c3 row+8
            int ex = nt * 8 + cq * 2 + (i & 1);
            lg[tk * 65 + ex] = run[nt][i];
        }
    __syncthreads();

    if (tid < MT) {
        float sc[NE];
#pragma unroll
        for (int e = 0; e < NE; e++) sc[e] = lg[tid * 65 + e];

        float mx = -CUDART_INF_F;
#pragma unroll
        for (int e = 0; e < NE; e++) mx = fmaxf(mx, sc[e]);
        float sum = 0.0f;
#pragma unroll
        for (int e = 0; e < NE; e++) { sc[e] = __expf(sc[e] - mx); sum += sc[e]; }
        float inv = 1.0f / sum;
#pragma unroll
        for (int e = 0; e < NE; e++) sc[e] *= inv;

        const float* bs = (const float*)(sm + OFFB);
        unsigned long long taken = 0ull;
        const int t = t0 + tid;
        float* wout = out + (size_t)t * TOPK;
        float* iout = out + (size_t)TOKENS * TOPK + (size_t)t * TOPK;

#pragma unroll
        for (int sidx = 0; sidx < TOPK; sidx++) {
            float best = -CUDART_INF_F;
            float bsc = 0.0f;
            int be = 0;
#pragma unroll
            for (int e = 0; e < NE; e++) {
                float v = sc[e] + bs[e];
                bool ok = ((taken >> e) & 1ull) == 0ull;
                if (ok && v > best) { best = v; bsc = sc[e]; be = e; }
            }
            taken |= (1ull << be);
            wout[sidx] = bsc;        // ROUTE_SCALE == 1.0
            iout[sidx] = (float)be;
        }
    }
}

extern "C" void kernel_launch(void* const* d_in, const int* in_sizes, int n_in,
                              void* d_out, int out_size) {
    const float* x    = (const float*)d_in[0];
    const float* w    = (const float*)d_in[1];
    const float* bias = (const float*)d_in[2];
    float* out        = (float*)d_out;

    cudaFuncSetAttribute(gate_hmma_kernel,
                         cudaFuncAttributeMaxDynamicSharedMemorySize, SMEMSZ);

    split_w_kernel<<<(NE * DIM) / 256, 256>>>(w);
    gate_hmma_kernel<<<TOKENS / MT, NTH, SMEMSZ>>>(x, bias, out);
}

// round 8
// speedup vs baseline: 4.6344x; 1.5711x over previous
#include <cuda_runtime.h>
#include <cuda_fp16.h>
#include <math_constants.h>
#include <cstdint>

#define TOKENS  32768
#define DIM     2048
#define NE      64
#define TOPK    6
#define MT      128                 // tokens per CTA
#define KCH     32                  // K per chunk
#define NCH     (DIM / KCH)         // 64
#define NTH     256
#define WSCALE_INV 0.03125f         // w pre-scaled by 32 in split kernel

// smem map (dynamic): x 3x16KB | w 3x8KB | bias
#define OFFX    0
#define XBUF    16384
#define OFFW    49152
#define WBUF    8192
#define OFFB    73728
#define SMEMSZ  73984

// pre-split (fp16, w*32), pre-swizzled weights: [term][chunk][64 experts x 64B]
__device__ __align__(16) unsigned char g_wsw[2][NCH][NE * KCH * 2];

__device__ __forceinline__ unsigned su32(const void* p) {
    return (unsigned)__cvta_generic_to_shared(p);
}
__device__ __forceinline__ void cp16(unsigned d, const void* s) {
    asm volatile("cp.async.cg.shared.global [%0], [%1], 16;" :: "r"(d), "l"(s));
}
// 2-term fp16 split of (f0,f1): p1 = rn(f), p2 = rn(f - p1)  (residual exact in f32)
__device__ __forceinline__ void split2h(float f0, float f1, unsigned& p1, unsigned& p2) {
    __half2 h1 = __floats2half2_rn(f0, f1);
    p1 = *(unsigned*)&h1;
    float2 g = __half22float2(h1);
    __half2 h2 = __floats2half2_rn(f0 - g.x, f1 - g.y);
    p2 = *(unsigned*)&h2;
}
__device__ __forceinline__ void ldsm4(unsigned b[4], unsigned addr) {
    asm volatile("ldmatrix.sync.aligned.m8n8.x4.shared.b16 {%0,%1,%2,%3}, [%4];"
                 : "=r"(b[0]), "=r"(b[1]), "=r"(b[2]), "=r"(b[3]) : "r"(addr));
}
// accumulate: C += A*B (fp16 in, fp32 acc)
__device__ __forceinline__ void mma16816(float* c, const unsigned* a,
                                         unsigned b0, unsigned b1) {
    asm volatile(
        "mma.sync.aligned.m16n8k16.row.col.f32.f16.f16.f32 "
        "{%0,%1,%2,%3}, {%4,%5,%6,%7}, {%8,%9}, {%0,%1,%2,%3};"
        : "+f"(c[0]), "+f"(c[1]), "+f"(c[2]), "+f"(c[3])
        : "r"(a[0]), "r"(a[1]), "r"(a[2]), "r"(a[3]), "r"(b0), "r"(b1));
}
// zero-start: C = A*B
__device__ __forceinline__ void mma16816_z(float* c, const unsigned* a,
                                           unsigned b0, unsigned b1) {
    asm volatile(
        "mma.sync.aligned.m16n8k16.row.col.f32.f16.f16.f32 "
        "{%0,%1,%2,%3}, {%4,%5,%6,%7}, {%8,%9}, {%10,%11,%12,%13};"
        : "=f"(c[0]), "=f"(c[1]), "=f"(c[2]), "=f"(c[3])
        : "r"(a[0]), "r"(a[1]), "r"(a[2]), "r"(a[3]), "r"(b0), "r"(b1),
          "f"(0.0f), "f"(0.0f), "f"(0.0f), "f"(0.0f));
}

// ---- pre-kernel: 2-term fp16 split of 32*w, ldmatrix-swizzled rows of 64B ----
__global__ void split_w_kernel(const float* __restrict__ w) {
    int idx = blockIdx.x * 256 + threadIdx.x;     // e*DIM + k, < 131072
    int e = idx >> 11, k = idx & (DIM - 1);
    float v = w[idx] * 32.0f;                     // exact scale, undone in epilogue
    __half h1 = __float2half_rn(v);
    float f1 = __half2float(h1);
    __half h2 = __float2half_rn(v - f1);
    int c = k >> 5, kk = k & (KCH - 1);
    unsigned off = ((unsigned)e << 6) | ((unsigned)kk << 1);
    unsigned sw = off ^ (((off >> 7) & 3u) << 4);   // bits[5:4] ^= bits[8:7]
    *(unsigned short*)&g_wsw[0][c][sw] = *(unsigned short*)&h1;
    *(unsigned short*)&g_wsw[1][c][sw] = *(unsigned short*)&h2;
}

__global__ __launch_bounds__(NTH, 2)
void gate_hmma_kernel(const float* __restrict__ x,
                      const float* __restrict__ bias,
                      float* __restrict__ out) {
    extern __shared__ unsigned char sm[];

    const int tid = threadIdx.x;
    const int wid = tid >> 5;
    const int L   = tid & 31;
    const int r4  = L >> 2;          // 0..7
    const int cq  = L & 3;           // 0..3
    const int t0  = blockIdx.x * MT;

    if (tid < NE) ((float*)(sm + OFFB))[tid] = bias[tid];

    // ---- cp.async source/dest setup (slot-0 bases) ----
    const float* xsrc[4]; unsigned xdst[4];
#pragma unroll
    for (int i = 0; i < 4; i++) {
        int u = tid + NTH * i;               // 0..1023 = 128 tokens x 8 16B units
        int tt = u >> 3, q = u & 7;
        xsrc[i] = x + (size_t)(t0 + tt) * DIM + q * 4;
        unsigned off = ((unsigned)tt << 7) | ((unsigned)q << 4);
        xdst[i] = su32(sm + OFFX) + (off ^ ((off >> 3) & 0x70u));
    }
    const unsigned char* wsrc[2]; unsigned wdst[2];
#pragma unroll
    for (int i = 0; i < 2; i++) {
        int u = tid + NTH * i;               // 0..511 = 2 terms x 256 units
        int trm = u >> 8; unsigned o = (unsigned)(u & 255) << 4;
        wsrc[i] = &g_wsw[trm][0][o];
        wdst[i] = su32(sm + OFFW) + trm * 4096 + o;
    }

    // fp32 running logits (IEEE adds), drained once per chunk
    float run[8][4];
#pragma unroll
    for (int n = 0; n < 8; n++)
#pragma unroll
        for (int i = 0; i < 4; i++) run[n][i] = 0.0f;

    // prologue: chunks 0 and 1 -> slots 0 and 1
#pragma unroll
    for (int sl = 0; sl < 2; sl++) {
#pragma unroll
        for (int i = 0; i < 4; i++) { cp16(xdst[i] + sl * XBUF, xsrc[i]); xsrc[i] += KCH; }
#pragma unroll
        for (int i = 0; i < 2; i++) { cp16(wdst[i] + sl * WBUF, wsrc[i]); wsrc[i] += 4096; }
        asm volatile("cp.async.commit_group;");
    }

    const int R0 = wid * 16 + r4;           // thread's token rows R0, R0+8
    int slot = 0, pf = 2;

    for (int ch = 0; ch < NCH; ch++) {
        if (ch < NCH - 1) {
            asm volatile("cp.async.wait_group 1;");
        } else {
            asm volatile("cp.async.wait_group 0;");
        }
        __syncthreads();   // chunk ch visible; all warps done reading slot pf

        // prefetch chunk ch+2 into slot pf (read at chunk ch-1)
        if (ch + 2 < NCH) {
#pragma unroll
            for (int i = 0; i < 4; i++) { cp16(xdst[i] + pf * XBUF, xsrc[i]); xsrc[i] += KCH; }
#pragma unroll
            for (int i = 0; i < 2; i++) { cp16(wdst[i] + pf * WBUF, wsrc[i]); wsrc[i] += 4096; }
            asm volatile("cp.async.commit_group;");
        }

        const unsigned xb = su32(sm + OFFX) + slot * XBUF;
        const unsigned wb = su32(sm + OFFW) + slot * WBUF;

        float cc[8][4];                     // chunk-local tensor-core chains
#pragma unroll
        for (int s = 0; s < 2; s++) {       // two k16 steps per chunk
            // ---- A fragments: LDS pairs + 2-term fp16 split ----
            unsigned a1[4], a2[4];
#pragma unroll
            for (int half = 0; half < 2; half++) {
#pragma unroll
                for (int rowi = 0; rowi < 2; rowi++) {
                    int row = R0 + rowi * 8;
                    unsigned off = ((unsigned)row << 7)
                                 + ((unsigned)(s * 16 + cq * 2 + half * 8) << 2);
                    unsigned sw = off ^ ((off >> 3) & 0x70u);
                    float f0, f1;
                    asm volatile("ld.shared.v2.f32 {%0,%1}, [%2];"
                                 : "=f"(f0), "=f"(f1) : "r"(xb + sw));
                    int pi = half * 2 + rowi;   // a0,a1,a2,a3 order
                    split2h(f0, f1, a1[pi], a2[pi]);
                }
            }
            // ---- B terms + HMMA: 3 products per C per k-step ----
            const int m  = L >> 3;          // ldmatrix matrix id
            const int rr = L & 7;
#pragma unroll
            for (int p = 0; p < 4; p++) {
                int e = p * 16 + (m >> 1) * 8 + rr;
                unsigned off = ((unsigned)e << 6) + s * 32 + (m & 1) * 16;
                unsigned sw = off ^ (((off >> 7) & 3u) << 4);
                unsigned b1[4], b2[4];
                ldsm4(b1, wb + sw);             // w term 1
                ldsm4(b2, wb + 4096 + sw);      // w term 2
                if (s == 0) {
                    mma16816_z(cc[2 * p + 0], a1, b1[0], b1[1]);
                    mma16816_z(cc[2 * p + 1], a1, b1[2], b1[3]);
                } else {
                    mma16816(cc[2 * p + 0], a1, b1[0], b1[1]);
                    mma16816(cc[2 * p + 1], a1, b1[2], b1[3]);
                }
                mma16816(cc[2 * p + 0], a2, b1[0], b1[1]);
                mma16816(cc[2 * p + 1], a2, b1[2], b1[3]);
                mma16816(cc[2 * p + 0], a1, b2[0], b2[1]);
                mma16816(cc[2 * p + 1], a1, b2[2], b2[3]);
            }
        }
        // ---- drain once per chunk: IEEE fp32 adds ----
#pragma unroll
        for (int nt = 0; nt < 8; nt++)
#pragma unroll
            for (int i = 0; i < 4; i++) run[nt][i] += cc[nt][i];

        slot = (slot == 2) ? 0 : slot + 1;
        pf   = (pf   == 2) ? 0 : pf   + 1;
    }

    __syncthreads();   // all warps done with mainloop buffers before overlay

    // ---- scatter logits to smem [128][65] (overlays mainloop buffers) ----
    float* lg = (float*)sm;
#pragma unroll
    for (int nt = 0; nt < 8; nt++)
#pragma unroll
        for (int i = 0; i < 4; i++) {
            int tk = R0 + ((i >= 2) ? 8 : 0);         // c0,c1 row; c2,c3 row+8
            int ex = nt * 8 + cq * 2 + (i & 1);
            lg[tk * 65 + ex] = run[nt][i];
        }
    __syncthreads();

    if (tid < MT) {
        float sc[NE];
#pragma unroll
        for (int e = 0; e < NE; e++) sc[e] = lg[tid * 65 + e] * WSCALE_INV;  // undo w*32

        float mx = -CUDART_INF_F;
#pragma unroll
        for (int e = 0; e < NE; e++) mx = fmaxf(mx, sc[e]);
        float sum = 0.0f;
#pragma unroll
        for (int e = 0; e < NE; e++) { sc[e] = __expf(sc[e] - mx); sum += sc[e]; }
        float inv = 1.0f / sum;
#pragma unroll
        for (int e = 0; e < NE; e++) sc[e] *= inv;

        const float* bs = (const float*)(sm + OFFB);
        unsigned long long taken = 0ull;
        const int t = t0 + tid;
        float* wout = out + (size_t)t * TOPK;
        float* iout = out + (size_t)TOKENS * TOPK + (size_t)t * TOPK;

#pragma unroll
        for (int sidx = 0; sidx < TOPK; sidx++) {
            float best = -CUDART_INF_F;
            float bsc = 0.0f;
            int be = 0;
#pragma unroll
            for (int e = 0; e < NE; e++) {
                float v = sc[e] + bs[e];
                bool ok = ((taken >> e) & 1ull) == 0ull;
                if (ok && v > best) { best = v; bsc = sc[e]; be = e; }
            }
            taken |= (1ull << be);
            wout[sidx] = bsc;        // ROUTE_SCALE == 1.0
            iout[sidx] = (float)be;
        }
    }
}

extern "C" void kernel_launch(void* const* d_in, const int* in_sizes, int n_in,
                              void* d_out, int out_size) {
    const float* x    = (const float*)d_in[0];
    const float* w    = (const float*)d_in[1];
    const float* bias = (const float*)d_in[2];
    float* out        = (float*)d_out;

    cudaFuncSetAttribute(gate_hmma_kernel,
                         cudaFuncAttributeMaxDynamicSharedMemorySize, SMEMSZ);

    split_w_kernel<<<(NE * DIM) / 256, 256>>>(w);
    gate_hmma_kernel<<<TOKENS / MT, NTH, SMEMSZ>>>(x, bias, out);
}